// round 13
// baseline (speedup 1.0000x reference)
#include <cuda_runtime.h>
#include <cuda_bf16.h>
#include <cstdint>

// Problem constants
#define BATCH   2
#define TSEQ    2048
#define NHEAD   16
#define DHEAD   64
#define DMODEL  1024
#define BH      (BATCH * NHEAD)        // 32
#define MROWS   (BATCH * TSEQ)         // 4096
#define N_QKV   (3 * NHEAD * DHEAD)    // 3072
#define ATTN_SCALE 0.125f              // 1/sqrt(64)
#define LN_EPS  1e-5f

// ---------------- scratch (static device globals; no allocations) ----------
__device__ __align__(16) uint32_t g_inp_bf [MROWS * DMODEL / 2];
__device__ __align__(16) uint32_t g_wqkv_bf[N_QKV * DMODEL / 2];
__device__ __align__(16) uint32_t g_wo_bf  [DMODEL * DMODEL / 2];
__device__ __align__(16) uint32_t g_qw [BH * TSEQ * 32];  // [bh][t][d/2]
__device__ __align__(16) uint32_t g_kw [BH * TSEQ * 32];
__device__ __align__(16) uint32_t g_vw [BH * TSEQ * 32];
__device__ __align__(16) uint32_t g_avw[BH * TSEQ * 32];  // attn out, L=b*16+h
__device__ float g_y[MROWS * DMODEL];                     // pre-LN fp32

// ---------------- helpers --------------------------------------------------
__device__ __forceinline__ uint32_t pack_bf16(float lo, float hi) {
    __nv_bfloat162 h = __floats2bfloat162_rn(lo, hi);
    return *reinterpret_cast<uint32_t*>(&h);
}

__device__ __forceinline__ uint32_t smem_u32(const void* p) {
    uint32_t a;
    asm("{ .reg .u64 t; cvta.to.shared.u64 t, %1; cvt.u32.u64 %0, t; }"
        : "=r"(a) : "l"(p));
    return a;
}

__device__ __forceinline__ void cp16(uint32_t s, const void* g) {
    asm volatile("cp.async.cg.shared.global [%0], [%1], 16;"
                 :: "r"(s), "l"(g) : "memory");
}
#define CP_COMMIT() asm volatile("cp.async.commit_group;" ::: "memory")
#define CP_WAIT(n)  asm volatile("cp.async.wait_group %0;" :: "n"(n) : "memory")

__device__ __forceinline__ void ldm_x4(uint32_t* r, uint32_t a) {
    asm volatile("ldmatrix.sync.aligned.m8n8.x4.shared.b16 {%0,%1,%2,%3}, [%4];"
                 : "=r"(r[0]), "=r"(r[1]), "=r"(r[2]), "=r"(r[3]) : "r"(a));
}
__device__ __forceinline__ void ldm_x4_t(uint32_t* r, uint32_t a) {
    asm volatile("ldmatrix.sync.aligned.m8n8.x4.trans.shared.b16 {%0,%1,%2,%3}, [%4];"
                 : "=r"(r[0]), "=r"(r[1]), "=r"(r[2]), "=r"(r[3]) : "r"(a));
}

// mma.sync m16n8k16 bf16 (fp32 accum).
__device__ __forceinline__ void mma_bf16(float* c, const uint32_t* a,
                                         uint32_t b0, uint32_t b1) {
    asm volatile(
        "mma.sync.aligned.m16n8k16.row.col.f32.bf16.bf16.f32 "
        "{%0,%1,%2,%3}, {%4,%5,%6,%7}, {%8,%9}, {%0,%1,%2,%3};"
        : "+f"(c[0]), "+f"(c[1]), "+f"(c[2]), "+f"(c[3])
        : "r"(a[0]), "r"(a[1]), "r"(a[2]), "r"(a[3]), "r"(b0), "r"(b1));
}

#define GSTW 36           // smem row stride in words (4 mod 32 -> conflict-free)
#define ROWB (GSTW * 4)   // 144 bytes

// ===========================================================================
// Kernel 0: one-time fp32 -> bf16 pre-convert of inp / W_qkv / W_o.
// ===========================================================================
#define CVT_T1 (MROWS * DMODEL / 4)
#define CVT_T2 (N_QKV * DMODEL / 4)
#define CVT_T3 (DMODEL * DMODEL / 4)
#define CVT_TOTAL (CVT_T1 + CVT_T2 + CVT_T3)

__global__ __launch_bounds__(256) void cvt_kernel(
    const float* __restrict__ inp,
    const float* __restrict__ wqkv,
    const float* __restrict__ wo)
{
    int idx = blockIdx.x * 256 + threadIdx.x;
    const float4* src;
    uint2* dst;
    int li;
    if (idx < CVT_T1) {
        src = (const float4*)inp;  dst = (uint2*)g_inp_bf;  li = idx;
    } else if (idx < CVT_T1 + CVT_T2) {
        src = (const float4*)wqkv; dst = (uint2*)g_wqkv_bf; li = idx - CVT_T1;
    } else {
        src = (const float4*)wo;   dst = (uint2*)g_wo_bf;   li = idx - CVT_T1 - CVT_T2;
    }
    float4 v = src[li];
    dst[li] = make_uint2(pack_bf16(v.x, v.y), pack_bf16(v.z, v.w));
}

// ===========================================================================
// Projection GEMMs: block 256(m) x 128(n), 8 warps as 4m x 2n, WARP TILE
// 64x64 (128 fp32 acc regs/thread), k-chunk 64 bf16, 3-stage cp.async
// pipeline, ldmatrix fragments. 1 CTA/SM (reg-bound) — tensor-density play:
// per kk step 8 LDSM feed 32 MMA (was 6:16), LDSM bytes/FLOP 1.5x lower.
// Smem words: A stages s*9216 (256 rows x 36), B stages 27648 + s*4608.
// ===========================================================================
#define NSTAGE   3
#define A_STG_W  (256 * GSTW)          // 9216 words
#define B_STG_W  (128 * GSTW)          // 4608 words
#define B_BASE_W (NSTAGE * A_STG_W)    // 27648
#define GEMM_SMEM_BYTES ((NSTAGE * (A_STG_W + B_STG_W)) * 4)  // 165888

// ---- Kernel 1: QKV ----
__device__ __forceinline__ void qkv_issue(
    uint32_t sbase, const char* gA, const char* gB, int kt, int stg, int tid)
{
    const uint32_t sa  = sbase + stg * A_STG_W * 4;
    const uint32_t sbb = sbase + (B_BASE_W + stg * B_STG_W) * 4;
#pragma unroll
    for (int p = 0; p < 8; p++) {          // A: 256 rows x 8 = 2048 copies
        int c = tid + p * 256;
        int row = c >> 3, col = c & 7;
        cp16(sa + row * ROWB + col * 16,
             gA + (size_t)row * 2048 + kt * 128 + col * 16);
    }
#pragma unroll
    for (int p = 0; p < 4; p++) {          // B: 128 rows x 8 = 1024 copies
        int c = tid + p * 256;
        int row = c >> 3, col = c & 7;
        cp16(sbb + row * ROWB + col * 16,
             gB + (size_t)row * 2048 + kt * 128 + col * 16);
    }
}

__global__ __launch_bounds__(256, 1) void qkv_gemm_kernel(
    const float* __restrict__ bias)
{
    extern __shared__ __align__(16) uint32_t smw[];
    const uint32_t sb = smem_u32(smw);

    const int tid  = threadIdx.x;
    const int lane = tid & 31;
    const int warp = tid >> 5;
    const int gid  = lane >> 2;
    const int tg   = lane & 3;
    const int wm   = warp & 3;          // 64-row group
    const int wn   = warp >> 2;         // 64-col group
    const int mBase = blockIdx.y * 256;
    const int nBase = blockIdx.x * 128;

    const int lr  = lane & 15;
    const int lko = (lane >> 4) * 4;

    const char* gA = (const char*)g_inp_bf  + (size_t)mBase * 2048;
    const char* gB = (const char*)g_wqkv_bf + (size_t)nBase * 2048;

    float acc[4][8][4];
#pragma unroll
    for (int mi = 0; mi < 4; mi++)
#pragma unroll
        for (int ni = 0; ni < 8; ni++)
#pragma unroll
            for (int j = 0; j < 4; j++) acc[mi][ni][j] = 0.f;

    qkv_issue(sb, gA, gB, 0, 0, tid); CP_COMMIT();
    qkv_issue(sb, gA, gB, 1, 1, tid); CP_COMMIT();

    for (int kt = 0; kt < 16; kt++) {
        const int stg = kt % NSTAGE;
        CP_WAIT(1);
        __syncthreads();

        const uint32_t abase = sb + stg * A_STG_W * 4;
        const uint32_t bbase = sb + (B_BASE_W + stg * B_STG_W) * 4;
#pragma unroll
        for (int kk = 0; kk < 32; kk += 8) {
            uint32_t af[4][4];
#pragma unroll
            for (int mi = 0; mi < 4; mi++)
                ldm_x4(af[mi], abase +
                       ((wm * 64 + mi * 16 + lr) * GSTW + kk + lko) * 4);
#pragma unroll
            for (int p = 0; p < 4; p++) {
                uint32_t bf[4];
                ldm_x4(bf, bbase +
                       ((wn * 64 + p * 16 + lr) * GSTW + kk + lko) * 4);
#pragma unroll
                for (int mi = 0; mi < 4; mi++) {
                    mma_bf16(acc[mi][2 * p],     af[mi], bf[0], bf[2]);
                    mma_bf16(acc[mi][2 * p + 1], af[mi], bf[1], bf[3]);
                }
            }
        }
        if (kt + 2 < 16)
            qkv_issue(sb, gA, gB, kt + 2, (kt + 2) % NSTAGE, tid);
        CP_COMMIT();   // uniform group count (empty groups at tail)
    }

    // epilogue: +bias, pack bf16 pair, scatter into q/k/v word arrays
#pragma unroll
    for (int mi = 0; mi < 4; mi++) {
        int r0 = mBase + wm * 64 + mi * 16 + gid;
        int r1 = r0 + 8;
        int bb0 = r0 >> 11, t0 = r0 & 2047;
        int bb1 = r1 >> 11, t1 = r1 & 2047;
#pragma unroll
        for (int ni = 0; ni < 8; ni++) {
            int n = nBase + wn * 64 + ni * 8 + tg * 2;
            int third = n >> 10;
            int nn = n & 1023;
            int h = nn >> 6, d = nn & 63;
            uint32_t* base = (third == 0) ? g_qw : ((third == 1) ? g_kw : g_vw);
            float2 bi = *(const float2*)(bias + n);
            base[((bb0 * NHEAD + h) * TSEQ + t0) * 32 + d / 2] =
                pack_bf16(acc[mi][ni][0] + bi.x, acc[mi][ni][1] + bi.y);
            base[((bb1 * NHEAD + h) * TSEQ + t1) * 32 + d / 2] =
                pack_bf16(acc[mi][ni][2] + bi.x, acc[mi][ni][3] + bi.y);
        }
    }
}

// ===========================================================================
// Kernel 2: flash attention, register softmax + ldmatrix frags (as R11).
// ===========================================================================
#define QB_OFF  0
#define KB_OFF  (128 * GSTW)                     // 4608
#define VS_OFF  (KB_OFF + 2 * 64 * GSTW)         // 9216
#define ATTN_SMEM_WORDS (VS_OFF + 2 * 64 * GSTW) // 13824
#define ATTN_SMEM_BYTES (ATTN_SMEM_WORDS * 4)    // 55296

__global__ __launch_bounds__(256) void attn_kernel()
{
    extern __shared__ __align__(16) uint32_t smw[];
    const uint32_t sb = smem_u32(smw);

    const int tid  = threadIdx.x;
    const int lane = tid & 31;
    const int warp = tid >> 5;
    const int gid  = lane >> 2;
    const int tg   = lane & 3;
    const int bh   = blockIdx.y;
    const int q0   = blockIdx.x * 128;

    const int lr  = lane & 15;
    const int lko = (lane >> 4) * 4;

    auto kv_issue = [&](int kt, int buf) {
        const char* gk = (const char*)g_kw + (size_t)(bh * TSEQ + kt * 64) * 128;
        const char* gv = (const char*)g_vw + (size_t)(bh * TSEQ + kt * 64) * 128;
        const uint32_t kbb = sb + (KB_OFF + buf * 64 * GSTW) * 4;
        const uint32_t vbb = sb + (VS_OFF + buf * 64 * GSTW) * 4;
#pragma unroll
        for (int p = 0; p < 2; p++) {
            int c = tid + p * 256;
            int row = c >> 3, col = c & 7;
            cp16(kbb + row * ROWB + col * 16, gk + row * 128 + col * 16);
            cp16(vbb + row * ROWB + col * 16, gv + row * 128 + col * 16);
        }
    };

    kv_issue(0, 0);
    CP_COMMIT();
    {
        const int qr = tid >> 1;
        const int hb = (tid & 1) * 16;
        const uint32_t* gq = g_qw + (size_t)(bh * TSEQ + q0 + qr) * 32 + hb;
        uint32_t* qrow = &smw[QB_OFF + qr * GSTW + hb];
#pragma unroll
        for (int i = 0; i < 4; i++)
            *(uint4*)&qrow[i * 4] = *(const uint4*)(gq + i * 4);
    }
    CP_WAIT(0);
    __syncthreads();

    uint32_t qf[4][4];
#pragma unroll
    for (int j = 0; j < 4; j++)
        ldm_x4(qf[j], sb + (QB_OFF + (warp * 16 + lr) * GSTW + j * 8 + lko) * 4);

    float oacc[8][4];
#pragma unroll
    for (int ni = 0; ni < 8; ni++)
#pragma unroll
        for (int j = 0; j < 4; j++) oacc[ni][j] = 0.f;
    float m0 = -1e30f, m1 = -1e30f, l0 = 0.f, l1 = 0.f;

    for (int kt = 0; kt < TSEQ / 64; kt++) {
        const int buf = kt & 1;
        if (kt < TSEQ / 64 - 1) {
            kv_issue(kt + 1, buf ^ 1);
            CP_COMMIT();
        }

        float s[8][4];
#pragma unroll
        for (int ni = 0; ni < 8; ni++)
#pragma unroll
            for (int j = 0; j < 4; j++) s[ni][j] = 0.f;
        const uint32_t kbase = sb + (KB_OFF + buf * 64 * GSTW) * 4;
#pragma unroll
        for (int j = 0; j < 4; j++) {
#pragma unroll
            for (int p = 0; p < 4; p++) {
                uint32_t bf[4];
                ldm_x4(bf, kbase + ((p * 16 + lr) * GSTW + j * 8 + lko) * 4);
                mma_bf16(s[2 * p],     qf[j], bf[0], bf[2]);
                mma_bf16(s[2 * p + 1], qf[j], bf[1], bf[3]);
            }
        }

        float mx0 = -1e30f, mx1 = -1e30f;
#pragma unroll
        for (int ni = 0; ni < 8; ni++) {
            s[ni][0] *= ATTN_SCALE; s[ni][1] *= ATTN_SCALE;
            s[ni][2] *= ATTN_SCALE; s[ni][3] *= ATTN_SCALE;
            mx0 = fmaxf(mx0, fmaxf(s[ni][0], s[ni][1]));
            mx1 = fmaxf(mx1, fmaxf(s[ni][2], s[ni][3]));
        }
        mx0 = fmaxf(mx0, __shfl_xor_sync(0xFFFFFFFFu, mx0, 1));
        mx0 = fmaxf(mx0, __shfl_xor_sync(0xFFFFFFFFu, mx0, 2));
        mx1 = fmaxf(mx1, __shfl_xor_sync(0xFFFFFFFFu, mx1, 1));
        mx1 = fmaxf(mx1, __shfl_xor_sync(0xFFFFFFFFu, mx1, 2));
        const float nm0 = fmaxf(m0, mx0), nm1 = fmaxf(m1, mx1);
        const float cr0 = __expf(m0 - nm0), cr1 = __expf(m1 - nm1);
        m0 = nm0; m1 = nm1;

        float sum0 = 0.f, sum1 = 0.f;
#pragma unroll
        for (int ni = 0; ni < 8; ni++) {
            s[ni][0] = __expf(s[ni][0] - nm0);
            s[ni][1] = __expf(s[ni][1] - nm0);
            s[ni][2] = __expf(s[ni][2] - nm1);
            s[ni][3] = __expf(s[ni][3] - nm1);
            sum0 += s[ni][0] + s[ni][1];
            sum1 += s[ni][2] + s[ni][3];
        }
        sum0 += __shfl_xor_sync(0xFFFFFFFFu, sum0, 1);
        sum0 += __shfl_xor_sync(0xFFFFFFFFu, sum0, 2);
        sum1 += __shfl_xor_sync(0xFFFFFFFFu, sum1, 1);
        sum1 += __shfl_xor_sync(0xFFFFFFFFu, sum1, 2);
        l0 = l0 * cr0 + sum0;
        l1 = l1 * cr1 + sum1;

        uint32_t pf[4][4];
#pragma unroll
        for (int j = 0; j < 4; j++) {
            pf[j][0] = pack_bf16(s[2 * j][0],     s[2 * j][1]);
            pf[j][1] = pack_bf16(s[2 * j][2],     s[2 * j][3]);
            pf[j][2] = pack_bf16(s[2 * j + 1][0], s[2 * j + 1][1]);
            pf[j][3] = pack_bf16(s[2 * j + 1][2], s[2 * j + 1][3]);
        }

#pragma unroll
        for (int ni = 0; ni < 8; ni++) {
            oacc[ni][0] *= cr0; oacc[ni][1] *= cr0;
            oacc[ni][2] *= cr1; oacc[ni][3] *= cr1;
        }

        const uint32_t vbase = sb + (VS_OFF + buf * 64 * GSTW) * 4;
#pragma unroll
        for (int j = 0; j < 4; j++) {
#pragma unroll
            for (int p = 0; p < 4; p++) {
                uint32_t vf[4];
                ldm_x4_t(vf, vbase + (j * 16 + lr) * ROWB + p * 32 + (lane >> 4) * 16);
                mma_bf16(oacc[2 * p],     pf[j], vf[0], vf[1]);
                mma_bf16(oacc[2 * p + 1], pf[j], vf[2], vf[3]);
            }
        }

        if (kt < TSEQ / 64 - 1) CP_WAIT(0);
        __syncthreads();
    }

    const float il0 = 1.0f / l0, il1 = 1.0f / l1;
    const int r0 = q0 + warp * 16 + gid;
    const int r1 = r0 + 8;
#pragma unroll
    for (int ni = 0; ni < 8; ni++) {
        int cw = (ni * 8 + tg * 2) / 2;
        g_avw[(size_t)(bh * TSEQ + r0) * 32 + cw] =
            pack_bf16(oacc[ni][0] * il0, oacc[ni][1] * il0);
        g_avw[(size_t)(bh * TSEQ + r1) * 32 + cw] =
            pack_bf16(oacc[ni][2] * il1, oacc[ni][3] * il1);
    }
}

// ===========================================================================
// Kernel 3: O-projection + residual, block 256x128, warp tile 64x64,
// 3-stage pipeline. A = av_perm (chunk kt -> head h2 = kt).
// ===========================================================================
__global__ __launch_bounds__(256, 1) void oproj_kernel(
    const float* __restrict__ inp)
{
    extern __shared__ __align__(16) uint32_t smw[];
    const uint32_t sb = smem_u32(smw);

    const int tid  = threadIdx.x;
    const int lane = tid & 31;
    const int warp = tid >> 5;
    const int gid  = lane >> 2;
    const int tg   = lane & 3;
    const int wm   = warp & 3;
    const int wn   = warp >> 2;
    const int mBase = blockIdx.y * 256;
    const int nBase = blockIdx.x * 128;

    const int lr  = lane & 15;
    const int lko = (lane >> 4) * 4;

    const char* gB = (const char*)g_wo_bf + (size_t)nBase * 2048;

    float acc[4][8][4];
#pragma unroll
    for (int mi = 0; mi < 4; mi++)
#pragma unroll
        for (int ni = 0; ni < 8; ni++)
#pragma unroll
            for (int j = 0; j < 4; j++) acc[mi][ni][j] = 0.f;

    auto issue = [&](int kt, int stg) {
        const uint32_t sa  = sb + stg * A_STG_W * 4;
        const uint32_t sbb = sb + (B_BASE_W + stg * B_STG_W) * 4;
#pragma unroll
        for (int p = 0; p < 8; p++) {      // A: 256 rows (permuted source)
            int c = tid + p * 256;
            int row = c >> 3, col = c & 7;
            int m = mBase + row;
            int b2 = m >> 11, t = m & 2047;
            const char* ga = (const char*)g_avw +
                ((size_t)(kt * BATCH + b2) * TSEQ + t) * 128 + col * 16;
            cp16(sa + row * ROWB + col * 16, ga);
        }
#pragma unroll
        for (int p = 0; p < 4; p++) {      // B: 128 rows
            int c = tid + p * 256;
            int row = c >> 3, col = c & 7;
            cp16(sbb + row * ROWB + col * 16,
                 gB + (size_t)row * 2048 + kt * 128 + col * 16);
        }
    };

    issue(0, 0); CP_COMMIT();
    issue(1, 1); CP_COMMIT();

    for (int kt = 0; kt < 16; kt++) {
        const int stg = kt % NSTAGE;
        CP_WAIT(1);
        __syncthreads();

        const uint32_t abase = sb + stg * A_STG_W * 4;
        const uint32_t bbase = sb + (B_BASE_W + stg * B_STG_W) * 4;
#pragma unroll
        for (int kk = 0; kk < 32; kk += 8) {
            uint32_t af[4][4];
#pragma unroll
            for (int mi = 0; mi < 4; mi++)
                ldm_x4(af[mi], abase +
                       ((wm * 64 + mi * 16 + lr) * GSTW + kk + lko) * 4);
#pragma unroll
            for (int p = 0; p < 4; p++) {
                uint32_t bf[4];
                ldm_x4(bf, bbase +
                       ((wn * 64 + p * 16 + lr) * GSTW + kk + lko) * 4);
#pragma unroll
                for (int mi = 0; mi < 4; mi++) {
                    mma_bf16(acc[mi][2 * p],     af[mi], bf[0], bf[2]);
                    mma_bf16(acc[mi][2 * p + 1], af[mi], bf[1], bf[3]);
                }
            }
        }
        if (kt + 2 < 16)
            issue(kt + 2, (kt + 2) % NSTAGE);
        CP_COMMIT();
    }

    // epilogue: residual add (fp32), write g_y
#pragma unroll
    for (int mi = 0; mi < 4; mi++) {
        int r0 = mBase + wm * 64 + mi * 16 + gid;
        int r1 = r0 + 8;
#pragma unroll
        for (int ni = 0; ni < 8; ni++) {
            int n = nBase + wn * 64 + ni * 8 + tg * 2;
            float2 i0 = *(const float2*)(inp + (size_t)r0 * DMODEL + n);
            float2 i1 = *(const float2*)(inp + (size_t)r1 * DMODEL + n);
            *(float2*)(g_y + (size_t)r0 * DMODEL + n) =
                make_float2(acc[mi][ni][0] + i0.x, acc[mi][ni][1] + i0.y);
            *(float2*)(g_y + (size_t)r1 * DMODEL + n) =
                make_float2(acc[mi][ni][2] + i1.x, acc[mi][ni][3] + i1.y);
        }
    }
}

// ===========================================================================
// Kernel 4: LayerNorm. One warp per row of 1024.
// ===========================================================================
__global__ __launch_bounds__(256) void ln_kernel(
    const float* __restrict__ gamma,
    const float* __restrict__ beta,
    float* __restrict__ out)
{
    const int row  = blockIdx.x * 8 + (threadIdx.x >> 5);
    const int lane = threadIdx.x & 31;
    const float* x = g_y + (size_t)row * DMODEL;

    float4 v[8];
    float s1 = 0.f, s2 = 0.f;
#pragma unroll
    for (int i = 0; i < 8; i++) {
        v[i] = *(const float4*)(x + lane * 4 + i * 128);
        s1 += v[i].x + v[i].y + v[i].z + v[i].w;
        s2 += v[i].x * v[i].x + v[i].y * v[i].y + v[i].z * v[i].z + v[i].w * v[i].w;
    }
#pragma unroll
    for (int off = 16; off > 0; off >>= 1) {
        s1 += __shfl_xor_sync(0xFFFFFFFFu, s1, off);
        s2 += __shfl_xor_sync(0xFFFFFFFFu, s2, off);
    }
    float mu   = s1 * (1.0f / DMODEL);
    float var  = s2 * (1.0f / DMODEL) - mu * mu;
    float rstd = rsqrtf(var + LN_EPS);

    float* o = out + (size_t)row * DMODEL;
#pragma unroll
    for (int i = 0; i < 8; i++) {
        int cbase = lane * 4 + i * 128;
        float4 g = *(const float4*)(gamma + cbase);
        float4 b = *(const float4*)(beta + cbase);
        float4 r;
        r.x = (v[i].x - mu) * rstd * g.x + b.x;
        r.y = (v[i].y - mu) * rstd * g.y + b.y;
        r.z = (v[i].z - mu) * rstd * g.z + b.z;
        r.w = (v[i].w - mu) * rstd * g.w + b.w;
        *(float4*)(o + cbase) = r;
    }
}

// ===========================================================================
extern "C" void kernel_launch(void* const* d_in, const int* in_sizes, int n_in,
                              void* d_out, int out_size)
{
    const float* inp   = (const float*)d_in[0];
    const float* Wqkv  = (const float*)d_in[1];
    const float* bqkv  = (const float*)d_in[2];
    const float* Wo    = (const float*)d_in[3];
    const float* gamma = (const float*)d_in[4];
    const float* beta  = (const float*)d_in[5];
    float* out = (float*)d_out;

    cudaFuncSetAttribute(qkv_gemm_kernel,
                         cudaFuncAttributeMaxDynamicSharedMemorySize,
                         GEMM_SMEM_BYTES);
    cudaFuncSetAttribute(oproj_kernel,
                         cudaFuncAttributeMaxDynamicSharedMemorySize,
                         GEMM_SMEM_BYTES);
    cudaFuncSetAttribute(attn_kernel,
                         cudaFuncAttributeMaxDynamicSharedMemorySize,
                         ATTN_SMEM_BYTES);

    cvt_kernel<<<CVT_TOTAL / 256, 256>>>(inp, Wqkv, Wo);
    qkv_gemm_kernel<<<dim3(N_QKV / 128, MROWS / 256), 256, GEMM_SMEM_BYTES>>>(bqkv);
    attn_kernel<<<dim3(TSEQ / 128, BH), 256, ATTN_SMEM_BYTES>>>();
    oproj_kernel<<<dim3(DMODEL / 128, MROWS / 256), 256, GEMM_SMEM_BYTES>>>(inp);
    ln_kernel<<<MROWS / 8, 256>>>(gamma, beta, out);
}